// round 2
// baseline (speedup 1.0000x reference)
#include <cuda_runtime.h>
#include <math.h>
#include <float.h>

#define NPIL 60000
#define PPTS 32

// 65 moment accumulators: [0..9] = sum(feats), [10..64] = upper-tri sum(feats x feats)
static __device__ float g_acc[65];
// per-channel folded params, 12 floats each (3 float4s):
// [0..3]=Wc (x,y,z,w merged+BN-scaled) [4..6]=a*W[4:7] [7..9]=a*W[7:10] [10]=b [11]=pad
static __device__ float g_params[64 * 12];
// per-pillar mean + center, precomputed by k_stats: [2i]={mx,my,mz,-}, [2i+1]={cx,cy,cz,-}
static __device__ float4 g_pm[NPIL * 2];

__global__ void k_init() {
    int t = threadIdx.x;
    if (t < 65) g_acc[t] = 0.0f;
}

__global__ void __launch_bounds__(256) k_stats(const float4* __restrict__ pts,
                                               const int* __restrict__ nvs,
                                               const int4* __restrict__ coords) {
    __shared__ float sred[8 * 65];
    const int lane = threadIdx.x & 31;
    const int warp = threadIdx.x >> 5;
    const int gw = blockIdx.x * 8 + warp;
    const int nw = gridDim.x * 8;

    float acc[65];
#pragma unroll
    for (int k = 0; k < 65; k++) acc[k] = 0.0f;

    for (int i = gw; i < NPIL; i += nw) {
        float4 q = pts[i * PPTS + lane];
        int nv = nvs[i];
        // sum of xyz over ALL 32 points (reference sums unmasked, divides by nv)
        float sx = q.x, sy = q.y, sz = q.z;
#pragma unroll
        for (int s = 16; s > 0; s >>= 1) {
            sx += __shfl_xor_sync(0xffffffffu, sx, s);
            sy += __shfl_xor_sync(0xffffffffu, sy, s);
            sz += __shfl_xor_sync(0xffffffffu, sz, s);
        }
        float inv = 1.0f / (float)nv;
        float mx = sx * inv, my = sy * inv, mz = sz * inv;
        int4 c = coords[i];
        float cx = (float)c.w * 0.2f + 0.1f;
        float cy = (float)c.z * 0.2f - 39.9f;
        float cz = (float)c.y * 4.0f - 1.0f;
        if (lane == 0) {
            g_pm[2 * i]     = make_float4(mx, my, mz, 0.0f);
            g_pm[2 * i + 1] = make_float4(cx, cy, cz, 0.0f);
        }
        float valid = (lane < nv) ? 1.0f : 0.0f;
        float f[10];
        f[0] = q.x * valid;        f[1] = q.y * valid;        f[2] = q.z * valid;
        f[3] = q.w * valid;
        f[4] = (q.x - mx) * valid; f[5] = (q.y - my) * valid; f[6] = (q.z - mz) * valid;
        f[7] = (q.x - cx) * valid; f[8] = (q.y - cy) * valid; f[9] = (q.z - cz) * valid;
#pragma unroll
        for (int k = 0; k < 10; k++) acc[k] += f[k];
        int idx = 10;
#pragma unroll
        for (int a = 0; a < 10; a++)
#pragma unroll
            for (int b = a; b < 10; b++)
                acc[idx++] += f[a] * f[b];
    }

#pragma unroll
    for (int k = 0; k < 65; k++) {
        float v = acc[k];
#pragma unroll
        for (int s = 16; s > 0; s >>= 1) v += __shfl_xor_sync(0xffffffffu, v, s);
        if (lane == 0) sred[warp * 65 + k] = v;
    }
    __syncthreads();
    int t = threadIdx.x;
    if (t < 65) {
        float s = 0.0f;
#pragma unroll
        for (int w = 0; w < 8; w++) s += sred[w * 65 + t];
        atomicAdd(&g_acc[t], s);
    }
}

__global__ void k_bn(const float* __restrict__ W, const float* __restrict__ gamma,
                     const float* __restrict__ beta) {
    int o = threadIdx.x;
    if (o >= 64) return;
    double w[10];
#pragma unroll
    for (int c = 0; c < 10; c++) w[c] = (double)W[o * 10 + c];
    const double NP = (double)NPIL * (double)PPTS;
    double mean = 0.0;
#pragma unroll
    for (int c = 0; c < 10; c++) mean += w[c] * (double)g_acc[c];
    mean /= NP;
    double e2 = 0.0;
    int idx = 10;
#pragma unroll
    for (int a = 0; a < 10; a++)
#pragma unroll
        for (int b = a; b < 10; b++) {
            double m = (double)g_acc[idx++];
            e2 += w[a] * w[b] * m * ((a == b) ? 1.0 : 2.0);
        }
    e2 /= NP;
    double var = e2 - mean * mean;
    double aa = (double)gamma[o] / sqrt(var + 1e-3);
    double bb = (double)beta[o] - mean * aa;
    float* p = g_params + o * 12;
    p[0] = (float)(aa * (w[0] + w[4] + w[7]));
    p[1] = (float)(aa * (w[1] + w[5] + w[8]));
    p[2] = (float)(aa * (w[2] + w[6] + w[9]));
    p[3] = (float)(aa * w[3]);
    p[4] = (float)(aa * w[4]);
    p[5] = (float)(aa * w[5]);
    p[6] = (float)(aa * w[6]);
    p[7] = (float)(aa * w[7]);
    p[8] = (float)(aa * w[8]);
    p[9] = (float)(aa * w[9]);
    p[10] = (float)bb;
    p[11] = 0.0f;
}

// Persistent, software-pipelined output kernel.
// Per warp: one pillar at a time; inner max loop over valid points (shared tile),
// pb dot uses precomputed (mean, center) from g_pm — no shuffles here.
// max_p(pb + d_p) == pb + max_p(d_p): pb applied after the loop.
__global__ void __launch_bounds__(128) k_out(const float4* __restrict__ pts,
                                             const int* __restrict__ nvs,
                                             float* __restrict__ out) {
    __shared__ float4 sp[4][2][32];
    const int lane = threadIdx.x & 31;
    const int warp = threadIdx.x >> 5;
    const int gw = blockIdx.x * 4 + warp;
    const int nw = gridDim.x * 4;

    // per-channel folded params: channel `lane` and `lane+32`
    const float4* pp = (const float4*)g_params;
    const float4 wc0 = pp[lane * 3 + 0];
    const float4 m0v = pp[lane * 3 + 1];   // {wm.x, wm.y, wm.z, wt.x}
    const float4 t0v = pp[lane * 3 + 2];   // {wt.y, wt.z, b, pad}
    const float4 wc1 = pp[(lane + 32) * 3 + 0];
    const float4 m1v = pp[(lane + 32) * 3 + 1];
    const float4 t1v = pp[(lane + 32) * 3 + 2];

    int i = gw;
    if (i >= NPIL) return;
    float4 q  = pts[(size_t)i * PPTS + lane];
    int    nv = nvs[i];
    float4 pm = g_pm[2 * i];
    float4 pc = g_pm[2 * i + 1];

    int buf = 0;
    for (;;) {
        sp[warp][buf][lane] = q;
        __syncwarp();

        const int inext = i + nw;
        const bool more = inext < NPIL;
        float4 qn, pmn, pcn;
        int nvn = 0;
        if (more) {  // prefetch next pillar while this one computes
            qn  = pts[(size_t)inext * PPTS + lane];
            nvn = nvs[inext];
            pmn = g_pm[2 * inext];
            pcn = g_pm[2 * inext + 1];
        }

        // pillar+channel bias (off the critical path of the max loop)
        const float pb0 = t0v.z - (pm.x * m0v.x + pm.y * m0v.y + pm.z * m0v.z)
                                - (pc.x * m0v.w + pc.y * t0v.x + pc.z * t0v.y);
        const float pb1 = t1v.z - (pm.x * m1v.x + pm.y * m1v.y + pm.z * m1v.z)
                                - (pc.x * m1v.w + pc.y * t1v.x + pc.z * t1v.y);

        const float4* s4 = sp[warp][buf];
        float a0 = -FLT_MAX, b0 = -FLT_MAX, a1 = -FLT_MAX, b1 = -FLT_MAX;
        int p = 0;
        for (; p + 2 <= nv; p += 2) {
            float4 r0 = s4[p];
            float4 r1 = s4[p + 1];
            float d00 = fmaf(r0.x, wc0.x, fmaf(r0.y, wc0.y, fmaf(r0.z, wc0.z, r0.w * wc0.w)));
            float d10 = fmaf(r0.x, wc1.x, fmaf(r0.y, wc1.y, fmaf(r0.z, wc1.z, r0.w * wc1.w)));
            float d01 = fmaf(r1.x, wc0.x, fmaf(r1.y, wc0.y, fmaf(r1.z, wc0.z, r1.w * wc0.w)));
            float d11 = fmaf(r1.x, wc1.x, fmaf(r1.y, wc1.y, fmaf(r1.z, wc1.z, r1.w * wc1.w)));
            a0 = fmaxf(a0, d00);
            b0 = fmaxf(b0, d01);
            a1 = fmaxf(a1, d10);
            b1 = fmaxf(b1, d11);
        }
        if (p < nv) {
            float4 r0 = s4[p];
            float d00 = fmaf(r0.x, wc0.x, fmaf(r0.y, wc0.y, fmaf(r0.z, wc0.z, r0.w * wc0.w)));
            float d10 = fmaf(r0.x, wc1.x, fmaf(r0.y, wc1.y, fmaf(r0.z, wc1.z, r0.w * wc1.w)));
            a0 = fmaxf(a0, d00);
            a1 = fmaxf(a1, d10);
        }

        float r0 = pb0 + fmaxf(a0, b0);
        float r1 = pb1 + fmaxf(a1, b1);
        if (nv < PPTS) {  // masked points contribute exactly b (pre-ReLU)
            r0 = fmaxf(r0, t0v.z);
            r1 = fmaxf(r1, t1v.z);
        }
        out[(size_t)i * 64 + lane]      = fmaxf(r0, 0.0f);
        out[(size_t)i * 64 + 32 + lane] = fmaxf(r1, 0.0f);

        if (!more) break;
        i = inext; q = qn; nv = nvn; pm = pmn; pc = pcn;
        buf ^= 1;
    }
}

extern "C" void kernel_launch(void* const* d_in, const int* in_sizes, int n_in,
                              void* d_out, int out_size) {
    const float4* feats  = (const float4*)d_in[0];
    const int*    nvs    = (const int*)d_in[1];
    const int4*   coords = (const int4*)d_in[2];
    const float*  W      = (const float*)d_in[3];
    const float*  gamma  = (const float*)d_in[4];
    const float*  beta   = (const float*)d_in[5];
    float* out = (float*)d_out;

    k_init<<<1, 128>>>();
    k_stats<<<296, 256>>>(feats, nvs, coords);
    k_bn<<<1, 64>>>(W, gamma, beta);
    k_out<<<1184, 128>>>(feats, nvs, out);
}